// round 8
// baseline (speedup 1.0000x reference)
#include <cuda_runtime.h>
#include <cuda_bf16.h>
#include <cstdint>

typedef __nv_bfloat16 bf16;

#define BB 4
#define SS 2048
#define NHD 16
#define DH 64
#define HH 1024
#define MTOT (BB*SS)     // 8192
#define KP3 3072         // 3*1024 packed K (projections)
#define KPS 192          // 3*64   packed K (QK)
#define KPV2 4096        // 2*2048 packed V (hi | lo)

#define ASLAB ((size_t)MTOT*KP3)
#define WSLAB ((size_t)HH*KP3)
#define LOG2E 1.4426950408889634f

// ------------------------- scratch (device globals) -------------------------
__device__ bf16  g_Xp[3*ASLAB];
__device__ bf16  g_Wt[4*WSLAB];
__device__ bf16  g_Qp[(size_t)BB*NHD*SS*KPS];
__device__ bf16  g_Kp[(size_t)BB*NHD*SS*KPS];
__device__ bf16  g_Vt[(size_t)BB*NHD*DH*KPV2];

// ------------------------- helpers -------------------------
__device__ __forceinline__ uint32_t s2u(const void* p) {
    uint32_t a;
    asm("{ .reg .u64 t; cvta.to.shared.u64 t, %1; cvt.u32.u64 %0, t; }" : "=r"(a) : "l"(p));
    return a;
}
#define CP_ASYNC16(dst, src) \
    asm volatile("cp.async.cg.shared.global [%0], [%1], 16;" :: "r"(dst), "l"(src))
#define CP_COMMIT() asm volatile("cp.async.commit_group;" ::: "memory")
#define CP_WAIT(n)  asm volatile("cp.async.wait_group %0;" :: "n"(n) : "memory")

__device__ __forceinline__ void ldm_x4(uint32_t* r, uint32_t addr) {
    asm volatile("ldmatrix.sync.aligned.m8n8.x4.shared.b16 {%0,%1,%2,%3}, [%4];"
        : "=r"(r[0]), "=r"(r[1]), "=r"(r[2]), "=r"(r[3]) : "r"(addr));
}
__device__ __forceinline__ void mma16816(float* d, const uint32_t* a, const uint32_t* b) {
    asm volatile("mma.sync.aligned.m16n8k16.row.col.f32.bf16.bf16.f32 "
        "{%0,%1,%2,%3}, {%4,%5,%6,%7}, {%8,%9}, {%0,%1,%2,%3};"
        : "+f"(d[0]), "+f"(d[1]), "+f"(d[2]), "+f"(d[3])
        : "r"(a[0]), "r"(a[1]), "r"(a[2]), "r"(a[3]), "r"(b[0]), "r"(b[1]));
}
__device__ __forceinline__ void split3(float f, bf16& hi, bf16& lo) {
    hi = __float2bfloat16(f);
    lo = __float2bfloat16(f - __bfloat162float(hi));
}
__device__ __forceinline__ uint32_t pk2(float lo, float hi) {
    uint32_t r;
    asm("cvt.rn.bf16x2.f32 %0, %1, %2;" : "=r"(r) : "f"(hi), "f"(lo));
    return r;
}
__device__ __forceinline__ float ex2f(float x) {
    float r;
    asm("ex2.approx.ftz.f32 %0, %1;" : "=f"(r) : "f"(x));
    return r;
}

// ------------------------- pack kernels -------------------------
__global__ __launch_bounds__(256) void pack_a_k(
    const float* __restrict__ q, const float* __restrict__ k,
    const float* __restrict__ v, bf16* __restrict__ xpBase)
{
    int z = blockIdx.y;
    const float* x = (z == 0) ? q : (z == 1) ? k : v;
    bf16* xp = xpBase + (size_t)z * ASLAB;
    int i = blockIdx.x * 256 + threadIdx.x;
    int row = i >> 8;
    int k4 = (i & 255) << 2;
    float4 f = *(const float4*)&x[((size_t)row << 10) + k4];
    float fv[4] = {f.x, f.y, f.z, f.w};
    bf16 h[4], l[4];
    #pragma unroll
    for (int qq = 0; qq < 4; qq++) split3(fv[qq], h[qq], l[qq]);
    size_t base = (size_t)row * KP3 + k4;
    *(__nv_bfloat162*)&xp[base]        = __nv_bfloat162(h[0], h[1]);
    *(__nv_bfloat162*)&xp[base + 2]    = __nv_bfloat162(h[2], h[3]);
    *(__nv_bfloat162*)&xp[base + 1024] = __nv_bfloat162(l[0], l[1]);
    *(__nv_bfloat162*)&xp[base + 1026] = __nv_bfloat162(l[2], l[3]);
    *(__nv_bfloat162*)&xp[base + 2048] = __nv_bfloat162(h[0], h[1]);
    *(__nv_bfloat162*)&xp[base + 2050] = __nv_bfloat162(h[2], h[3]);
}

__global__ __launch_bounds__(256) void pack_wt_k(
    const float* __restrict__ wq, const float* __restrict__ wk,
    const float* __restrict__ wv, const float* __restrict__ wo,
    bf16* __restrict__ wtBase)
{
    __shared__ float t[32][33];
    int z = blockIdx.z;
    const float* W = (z == 0) ? wq : (z == 1) ? wk : (z == 2) ? wv : wo;
    bf16* Wt = wtBase + (size_t)z * WSLAB;
    int tx = threadIdx.x & 31, ty = threadIdx.x >> 5;
    int n0 = blockIdx.x * 32, k0 = blockIdx.y * 32;
    #pragma unroll
    for (int r = 0; r < 4; r++) {
        int k = k0 + ty + r * 8;
        t[ty + r * 8][tx] = W[(size_t)k * HH + n0 + tx];
    }
    __syncthreads();
    #pragma unroll
    for (int r = 0; r < 4; r++) {
        int n = n0 + ty + r * 8;
        int k = k0 + tx;
        bf16 hi, lo; split3(t[tx][ty + r * 8], hi, lo);
        size_t base = (size_t)n * KP3 + k;
        Wt[base] = hi; Wt[base + 1024] = hi; Wt[base + 2048] = lo;
    }
}

// ------------------------- universal GEMM: 3-stage, CTA 128x256, warp 64x64 -------------------------
#define LDS2 72
#define BUFA (128*LDS2*2)   // 18432
#define BUFB (256*LDS2*2)   // 36864
#define STAGE (BUFA+BUFB)   // 55296

__global__ __launch_bounds__(256) void gemm_u(
    const bf16* __restrict__ Abase, const bf16* __restrict__ Wbase,
    float* __restrict__ outf, bf16* __restrict__ outq,
    bf16* __restrict__ outk, bf16* __restrict__ outvt,
    const float* __restrict__ b0, const float* __restrict__ b1,
    const float* __restrict__ b2, int fixedMode)
{
    extern __shared__ char smem[];
    const int tid = threadIdx.x, wid = tid >> 5, lane = tid & 31;
    const int m0 = blockIdx.y * 128, n0 = blockIdx.x * 256;
    const int z = blockIdx.z;
    const int epi = (fixedMode < 0) ? z : fixedMode;

    const uint32_t sb = s2u(smem);

    const bf16* Ab = Abase + ((fixedMode < 0) ? (size_t)z * ASLAB : 0) + (size_t)m0 * KP3;
    const bf16* Bb = Wbase + ((fixedMode < 0) ? (size_t)z * WSLAB : 0) + (size_t)n0 * KP3;
    const float* bias = (epi == 0) ? b0 : (epi == 1) ? b1 : (epi == 2) ? b2 : b0;
    const float scale = (epi == 0) ? (0.125f * LOG2E) : 1.0f;
    constexpr int nC = KP3 / 64;   // 48

    auto loadChunk = [&](int c, int s) {
        const uint32_t uA = sb + s * STAGE;
        const uint32_t uB = uA + BUFA;
        const bf16* ap = Ab + c * 64;
        const bf16* bp = Bb + c * 64;
        #pragma unroll
        for (int p = 0; p < 4; p++) {
            int idx = tid + p * 256;
            int r = idx >> 3, sg = idx & 7;
            CP_ASYNC16(uA + r * (LDS2 * 2) + sg * 16,
                       (const char*)(ap + (size_t)r * KP3) + sg * 16);
        }
        #pragma unroll
        for (int p = 0; p < 8; p++) {
            int idx = tid + p * 256;
            int r = idx >> 3, sg = idx & 7;
            CP_ASYNC16(uB + r * (LDS2 * 2) + sg * 16,
                       (const char*)(bp + (size_t)r * KP3) + sg * 16);
        }
        CP_COMMIT();
    };

    float acc[4][8][4];
    #pragma unroll
    for (int i = 0; i < 4; i++)
        #pragma unroll
        for (int j = 0; j < 8; j++)
            #pragma unroll
            for (int q = 0; q < 4; q++) acc[i][j][q] = 0.f;

    const int wm = (wid & 1) * 64;
    const int wn = (wid >> 1) * 64;

    loadChunk(0, 0);
    loadChunk(1, 1);
    for (int c = 0; c < nC; c++) {
        if (c + 1 < nC) CP_WAIT(1); else CP_WAIT(0);
        __syncthreads();
        if (c + 2 < nC) loadChunk(c + 2, (c + 2) % 3);
        const uint32_t uA = sb + (c % 3) * STAGE;
        const uint32_t uB = uA + BUFA;
        #pragma unroll
        for (int ks = 0; ks < 4; ks++) {
            uint32_t a[4][4];
            #pragma unroll
            for (int im = 0; im < 4; im++) {
                uint32_t addr = uA +
                    ((wm + im * 16 + (lane & 15)) * LDS2 + ks * 16 + (lane >> 4) * 8) * 2;
                ldm_x4(a[im], addr);
            }
            uint32_t b[4][4];
            #pragma unroll
            for (int ig = 0; ig < 4; ig++) {
                uint32_t addr = uB +
                    ((wn + ig * 16 + (lane & 7) + ((lane >> 4) << 3)) * LDS2
                     + ks * 16 + (((lane >> 3) & 1) << 3)) * 2;
                ldm_x4(b[ig], addr);
            }
            #pragma unroll
            for (int im = 0; im < 4; im++)
                #pragma unroll
                for (int ig = 0; ig < 4; ig++) {
                    mma16816(acc[im][ig * 2],     a[im], &b[ig][0]);
                    mma16816(acc[im][ig * 2 + 1], a[im], &b[ig][2]);
                }
        }
    }

    // ------------------- epilogues -------------------
    if (epi == 2) {
        // VT pack in two n-halves through a 128x130 fp32 stage
        float* stage = (float*)smem;
        const int bI = m0 >> 11, sBase = m0 & (SS - 1);
        #pragma unroll 1
        for (int half = 0; half < 2; half++) {
            __syncthreads();
            if ((wid >> 2) == half) {
                int nlBase = ((wid >> 1) & 1) * 64;
                #pragma unroll
                for (int im = 0; im < 4; im++)
                    #pragma unroll
                    for (int jn = 0; jn < 8; jn++)
                        #pragma unroll
                        for (int h2 = 0; h2 < 2; h2++)
                            #pragma unroll
                            for (int cc = 0; cc < 2; cc++) {
                                int ml = wm + im * 16 + (lane >> 2) + h2 * 8;
                                int nl = nlBase + jn * 8 + (lane & 3) * 2 + cc;
                                stage[ml * 130 + nl] =
                                    acc[im][jn][h2 * 2 + cc] + bias[n0 + half * 128 + nl];
                            }
            }
            __syncthreads();
            {
                int gl = tid >> 1;
                int gn = n0 + half * 128 + gl;
                int h = gn >> 6, d = gn & 63;
                size_t base = ((size_t)((bI * NHD + h) * DH + d)) * KPV2;
                int s0 = (tid & 1) * 64;
                #pragma unroll 4
                for (int s = 0; s < 64; s++) {
                    int sl = s0 + s;
                    bf16 hi, lo; split3(stage[sl * 130 + gl], hi, lo);
                    size_t sidx = base + sBase + sl;
                    outvt[sidx] = hi; outvt[sidx + 2048] = lo;
                }
            }
        }
    } else if (epi == 3) {
        #pragma unroll
        for (int im = 0; im < 4; im++)
            #pragma unroll
            for (int jn = 0; jn < 8; jn++)
                #pragma unroll
                for (int h2 = 0; h2 < 2; h2++) {
                    int m = m0 + wm + im * 16 + (lane >> 2) + h2 * 8;
                    int gn = n0 + wn + jn * 8 + (lane & 3) * 2;
                    float2 r2;
                    r2.x = acc[im][jn][h2 * 2]     + bias[gn];
                    r2.y = acc[im][jn][h2 * 2 + 1] + bias[gn + 1];
                    *(float2*)&outf[(size_t)m * HH + gn] = r2;
                }
    } else {
        #pragma unroll
        for (int im = 0; im < 4; im++)
            #pragma unroll
            for (int jn = 0; jn < 8; jn++)
                #pragma unroll
                for (int h2 = 0; h2 < 2; h2++) {
                    int m = m0 + wm + im * 16 + (lane >> 2) + h2 * 8;
                    int gn = n0 + wn + jn * 8 + (lane & 3) * 2;
                    float v0 = (acc[im][jn][h2 * 2]     + bias[gn])     * scale;
                    float v1 = (acc[im][jn][h2 * 2 + 1] + bias[gn + 1]) * scale;
                    int h = gn >> 6, d = gn & 63;
                    int bI = m >> 11, sI = m & (SS - 1);
                    uint32_t phi = pk2(v0, v1);
                    float fh0 = __uint_as_float(phi << 16);
                    float fh1 = __uint_as_float(phi & 0xffff0000u);
                    uint32_t plo = pk2(v0 - fh0, v1 - fh1);
                    size_t base = ((size_t)(bI * NHD + h) * SS + sI) * KPS;
                    if (epi == 0) {  // Q: A-side [hi|lo|hi]
                        *(uint32_t*)&outq[base + d]       = phi;
                        *(uint32_t*)&outq[base + 64 + d]  = plo;
                        *(uint32_t*)&outq[base + 128 + d] = phi;
                    } else {         // K: B-side [hi|hi|lo]
                        *(uint32_t*)&outk[base + d]       = phi;
                        *(uint32_t*)&outk[base + 64 + d]  = phi;
                        *(uint32_t*)&outk[base + 128 + d] = plo;
                    }
                }
    }
}

// ------------------------- fused flash attention: 64-key tiles, triple-buffered -------------------------
#define KSTR 200
#define KB1 (64*KSTR*2)      // 25600
#define VSTRF 72
#define VSEC (64*VSTRF*2)    // 9216
#define VB1 (2*VSEC)         // 18432
#define NIT 32

__global__ __launch_bounds__(256, 1) void flash_k(
    const bf16* __restrict__ Qp, const bf16* __restrict__ Kp,
    const bf16* __restrict__ Vt, bf16* __restrict__ Ctx)
{
    extern __shared__ char smem[];
    const int tid = threadIdx.x, wid = tid >> 5, lane = tid & 31;
    const int qt = blockIdx.x, bh = blockIdx.y;
    const int b_ = bh >> 4, h_ = bh & 15;
    const uint32_t sb = s2u(smem);
    const uint32_t uKb[3] = { sb, sb + KB1, sb + 2 * KB1 };
    const uint32_t uVb[3] = { sb + 3 * KB1, sb + 3 * KB1 + VB1, sb + 3 * KB1 + 2 * VB1 };

    const bf16* Qb = Qp + ((size_t)bh * SS + qt * 128) * KPS;
    const bf16* Kb = Kp + (size_t)bh * SS * KPS;
    const bf16* Vb = Vt + (size_t)bh * DH * KPV2;

    auto issueK = [&](int it) {
        const bf16* kp2 = Kb + (size_t)(it * 64) * KPS;
        uint32_t dst = uKb[it % 3];
        #pragma unroll
        for (int p = 0; p < 6; p++) {
            int idx = tid + p * 256;
            int r = idx / 24, sg = idx % 24;
            CP_ASYNC16(dst + r * (KSTR * 2) + sg * 16,
                       (const char*)(kp2 + (size_t)r * KPS) + sg * 16);
        }
        CP_COMMIT();
    };
    auto issueV = [&](int it) {
        uint32_t dst = uVb[it % 3];
        int kt = it * 64;
        #pragma unroll
        for (int p = 0; p < 2; p++) {
            int idx = tid + p * 256;
            int r = idx >> 3, sg = idx & 7;
            const char* s = (const char*)(Vb + (size_t)r * KPV2 + kt) + sg * 16;
            CP_ASYNC16(dst + r * (VSTRF * 2) + sg * 16, s);
            CP_ASYNC16(dst + VSEC + r * (VSTRF * 2) + sg * 16, s + 4096);
        }
        CP_COMMIT();
    };

    // prologue: Q staged across K bufs 0+1 (contiguous 51200 B)
    #pragma unroll
    for (int p = 0; p < 12; p++) {
        int idx = tid + p * 256;
        int r = idx / 24, sg = idx % 24;
        CP_ASYNC16(sb + r * (KSTR * 2) + sg * 16,
                   (const char*)(Qb + (size_t)r * KPS) + sg * 16);
    }
    CP_COMMIT();
    CP_WAIT(0); __syncthreads();

    uint32_t qf[12][4];
    {
        int rbase = wid * 16 + (lane & 15);
        #pragma unroll
        for (int kc = 0; kc < 12; kc++)
            ldm_x4(qf[kc], sb + (rbase * KSTR + kc * 16 + (lane >> 4) * 8) * 2);
    }
    __syncthreads();

    issueK(0); issueV(0); issueK(1); issueV(1);   // 4 pending groups

    float oacc[8][4];
    #pragma unroll
    for (int j = 0; j < 8; j++)
        #pragma unroll
        for (int q = 0; q < 4; q++) oacc[j][q] = 0.f;
    float M0 = -1e30f, M1 = -1e30f, L0 = 0.f, L1 = 0.f;

    for (int i = 0; i < NIT; i++) {
        if (i < NIT - 1) CP_WAIT(2); else CP_WAIT(0);
        __syncthreads();
        if (i + 2 < NIT) { issueK(i + 2); issueV(i + 2); }

        const uint32_t kbase = uKb[i % 3];
        const uint32_t vhi = uVb[i % 3], vlo = vhi + VSEC;

        // S = Q K^T  (16 rows x 64 keys per warp)
        float sc[8][4];
        #pragma unroll
        for (int t = 0; t < 8; t++)
            #pragma unroll
            for (int q = 0; q < 4; q++) sc[t][q] = 0.f;
        #pragma unroll
        for (int kc = 0; kc < 12; kc++) {
            #pragma unroll
            for (int kg = 0; kg < 4; kg++) {
                uint32_t b[4];
                uint32_t addr = kbase + ((kg * 16 + (lane & 7) + ((lane >> 4) << 3)) * KSTR
                                         + kc * 16 + (((lane >> 3) & 1) << 3)) * 2;
                ldm_x4(b, addr);
                mma16816(sc[kg * 2],     qf[kc], b);
                mma16816(sc[kg * 2 + 1], qf[kc], b + 2);
            }
        }

        // online softmax (log2 domain; Q pre-scaled by log2e/8)
        float m0 = -1e30f, m1 = -1e30f;
        #pragma unroll
        for (int t = 0; t < 8; t++) {
            m0 = fmaxf(m0, fmaxf(sc[t][0], sc[t][1]));
            m1 = fmaxf(m1, fmaxf(sc[t][2], sc[t][3]));
        }
        #pragma unroll
        for (int off = 1; off <= 2; off <<= 1) {
            m0 = fmaxf(m0, __shfl_xor_sync(0xffffffffu, m0, off));
            m1 = fmaxf(m1, __shfl_xor_sync(0xffffffffu, m1, off));
        }
        float nM0 = fmaxf(M0, m0), nM1 = fmaxf(M1, m1);
        float a0 = ex2f(M0 - nM0), a1 = ex2f(M1 - nM1);
        M0 = nM0; M1 = nM1;
        float s0 = 0.f, s1 = 0.f;
        #pragma unroll
        for (int t = 0; t < 8; t++) {
            sc[t][0] = ex2f(sc[t][0] - M0); s0 += sc[t][0];
            sc[t][1] = ex2f(sc[t][1] - M0); s0 += sc[t][1];
            sc[t][2] = ex2f(sc[t][2] - M1); s1 += sc[t][2];
            sc[t][3] = ex2f(sc[t][3] - M1); s1 += sc[t][3];
        }
        #pragma unroll
        for (int off = 1; off <= 2; off <<= 1) {
            s0 += __shfl_xor_sync(0xffffffffu, s0, off);
            s1 += __shfl_xor_sync(0xffffffffu, s1, off);
        }
        L0 = L0 * a0 + s0; L1 = L1 * a1 + s1;
        #pragma unroll
        for (int j = 0; j < 8; j++) {
            oacc[j][0] *= a0; oacc[j][1] *= a0;
            oacc[j][2] *= a1; oacc[j][3] *= a1;
        }

        // PV: 3 chains, keys split into 4 x 16
        #pragma unroll
        for (int j = 0; j < 4; j++) {
            uint32_t ph[4], pl[4];
            float c00 = sc[2*j][0],   c01 = sc[2*j][1];
            float c02 = sc[2*j][2],   c03 = sc[2*j][3];
            float c10 = sc[2*j+1][0], c11 = sc[2*j+1][1];
            float c12 = sc[2*j+1][2], c13 = sc[2*j+1][3];
            ph[0] = pk2(c00, c01); ph[1] = pk2(c02, c03);
            ph[2] = pk2(c10, c11); ph[3] = pk2(c12, c13);
            float h00 = __uint_as_float(ph[0] << 16), h01 = __uint_as_float(ph[0] & 0xffff0000u);
            float h02 = __uint_as_float(ph[1] << 16), h03 = __uint_as_float(ph[1] & 0xffff0000u);
            float h10 = __uint_as_float(ph[2] << 16), h11 = __uint_as_float(ph[2] & 0xffff0000u);
            float h12 = __uint_as_float(ph[3] << 16), h13 = __uint_as_float(ph[3] & 0xffff0000u);
            pl[0] = pk2(c00 - h00, c01 - h01); pl[1] = pk2(c02 - h02, c03 - h03);
            pl[2] = pk2(c10 - h10, c11 - h11); pl[3] = pk2(c12 - h12, c13 - h13);

            uint32_t koff = (j * 16 + (((lane >> 3) & 1) << 3)) * 2;
            uint32_t rsel = (lane & 7) + ((lane >> 4) << 3);
            #pragma unroll
            for (int dg = 0; dg < 4; dg++) {
                uint32_t row = dg * 16 + rsel;
                uint32_t bh4[4], bl4[4];
                ldm_x4(bh4, vhi + row * (VSTRF * 2) + koff);
                ldm_x4(bl4, vlo + row * (VSTRF * 2) + koff);
                mma16816(oacc[dg * 2],     ph, bh4);
                mma16816(oacc[dg * 2 + 1], ph, bh4 + 2);
                mma16816(oacc[dg * 2],     pl, bh4);
                mma16816(oacc[dg * 2 + 1], pl, bh4 + 2);
                mma16816(oacc[dg * 2],     ph, bl4);
                mma16816(oacc[dg * 2 + 1], ph, bl4 + 2);
            }
        }
    }

    // epilogue: normalize + packed ctx write [hi|lo|hi]
    float i0 = 1.f / L0, i1 = 1.f / L1;
    int r = lane >> 2;
    int q0 = qt * 128 + wid * 16;
    size_t row0 = ((size_t)(b_ * SS + q0 + r)) * KP3;
    size_t row1 = ((size_t)(b_ * SS + q0 + r + 8)) * KP3;
    int cbase = h_ * DH + (lane & 3) * 2;
    #pragma unroll
    for (int t = 0; t < 8; t++) {
        int col = cbase + t * 8;
        float v0 = oacc[t][0] * i0, v1 = oacc[t][1] * i0;
        float w0 = oacc[t][2] * i1, w1 = oacc[t][3] * i1;
        uint32_t pv = pk2(v0, v1);
        uint32_t pw = pk2(w0, w1);
        float vh0 = __uint_as_float(pv << 16), vh1 = __uint_as_float(pv & 0xffff0000u);
        float wh0 = __uint_as_float(pw << 16), wh1 = __uint_as_float(pw & 0xffff0000u);
        *(uint32_t*)&Ctx[row0 + col]        = pv;
        *(uint32_t*)&Ctx[row0 + 1024 + col] = pk2(v0 - vh0, v1 - vh1);
        *(uint32_t*)&Ctx[row0 + 2048 + col] = pv;
        *(uint32_t*)&Ctx[row1 + col]        = pw;
        *(uint32_t*)&Ctx[row1 + 1024 + col] = pk2(w0 - wh0, w1 - wh1);
        *(uint32_t*)&Ctx[row1 + 2048 + col] = pw;
    }
}

// ------------------------- launch -------------------------
extern "C" void kernel_launch(void* const* d_in, const int* in_sizes, int n_in,
                              void* d_out, int out_size)
{
    const float* key   = (const float*)d_in[0];
    const float* value = (const float*)d_in[1];
    const float* query = (const float*)d_in[2];
    const float* wq = (const float*)d_in[3];
    const float* bq = (const float*)d_in[4];
    const float* wk = (const float*)d_in[5];
    const float* bk = (const float*)d_in[6];
    const float* wv = (const float*)d_in[7];
    const float* bv = (const float*)d_in[8];
    const float* wo = (const float*)d_in[9];
    const float* bo = (const float*)d_in[10];
    float* out = (float*)d_out;

    bf16 *xp, *wt, *qp, *kp, *vt;
    cudaGetSymbolAddress((void**)&xp, g_Xp);
    cudaGetSymbolAddress((void**)&wt, g_Wt);
    cudaGetSymbolAddress((void**)&qp, g_Qp);
    cudaGetSymbolAddress((void**)&kp, g_Kp);
    cudaGetSymbolAddress((void**)&vt, g_Vt);

    constexpr int SMG  = 3 * STAGE;                 // 165888
    constexpr int SMFL = 3 * KB1 + 3 * VB1;         // 132096
    cudaFuncSetAttribute(gemm_u,  cudaFuncAttributeMaxDynamicSharedMemorySize, SMG);
    cudaFuncSetAttribute(flash_k, cudaFuncAttributeMaxDynamicSharedMemorySize, SMFL);

    pack_wt_k<<<dim3(32, 32, 4), 256>>>(wq, wk, wv, wo, wt);
    pack_a_k<<<dim3(MTOT * HH / 1024, 3), 256>>>(query, key, value, xp);

    // merged QKV projections (z: 0=Q,1=K,2=Vt), CTA 128x256
    gemm_u<<<dim3(4, 64, 3), 256, SMG>>>(xp, wt, nullptr, qp, kp, vt,
                                         bq, bk, bv, -1);

    // fused attention -> packed ctx in Xp slab 0
    flash_k<<<dim3(16, 64), 256, SMFL>>>(qp, kp, vt, xp);

    // output projection
    gemm_u<<<dim3(4, 64, 1), 256, SMG>>>(xp, wt + 3 * WSLAB, out,
                                         nullptr, nullptr, nullptr,
                                         bo, bo, bo, 3);
}